// round 10
// baseline (speedup 1.0000x reference)
#include <cuda_runtime.h>
#include <math.h>

#define BS   16
#define NP   4000
#define CC   80
#define GG   300
#define KTOP 13
#define NW   8              // warps per assign block
#define TPB  (NW * 32)      // 256 threads
#define NPW  (NP / NW)      // 500 preds per warp
#define JMAX ((NPW + 31) / 32)  // 16 strided iters per lane

typedef unsigned long long u64;
typedef unsigned int u32;

// Scratch (device globals; zero-initialized at load)
__device__ float g_scores_t[BS * CC * NP];   // sigmoid(logits) transposed [b][c][n]
__device__ u64   g_key[BS * NP];             // packed (mapped_overlap, ~g) per pred

struct Box { float x1, y1, x2, y2, area; };

__device__ __forceinline__ Box toxyxy(float4 b) {
    Box r;
    r.x1 = b.x - 0.5f * b.z;
    r.y1 = b.y - 0.5f * b.w;
    r.x2 = b.x + 0.5f * b.z;
    r.y2 = b.y + 0.5f * b.w;
    r.area = (r.x2 - r.x1) * (r.y2 - r.y1);
    return r;
}

// EXACT mirror of the reference arithmetic (order of ops matters for ranking)
__device__ __forceinline__ float neg_giou(const Box& a, const Box& b) {
    float ltx = fmaxf(a.x1, b.x1), lty = fmaxf(a.y1, b.y1);
    float rbx = fminf(a.x2, b.x2), rby = fminf(a.y2, b.y2);
    float wi = fmaxf(rbx - ltx, 0.f), hi = fmaxf(rby - lty, 0.f);
    float inter = wi * hi;
    float uni = a.area + b.area - inter;
    float iou = inter / uni;
    float lex = fminf(a.x1, b.x1), ley = fminf(a.y1, b.y1);
    float rex = fmaxf(a.x2, b.x2), rey = fmaxf(a.y2, b.y2);
    float we = fmaxf(rex - lex, 0.f), he = fmaxf(rey - ley, 0.f);
    float ae = we * he;
    float giou = iou - (ae - uni) / ae;
    return -giou;
}

__device__ __forceinline__ float pow6(float x) {
    float x2 = x * x;
    return x2 * x2 * x2;
}

// monotone map float -> u32 (order-preserving as unsigned), and inverse
__device__ __forceinline__ u32 fmap(float f) {
    u32 u = __float_as_uint(f);
    return (u & 0x80000000u) ? ~u : (u | 0x80000000u);
}
__device__ __forceinline__ float fmap_inv(u32 m) {
    u32 u = (m & 0x80000000u) ? (m & 0x7fffffffu) : ~m;
    return __uint_as_float(u);
}
__device__ __forceinline__ u64 pack_key(float v, u32 idx) {
    return ((u64)fmap(v) << 32) | (u64)(0xffffffffu - idx);
}

__device__ __forceinline__ u64 warp_max64(u64 v) {
#pragma unroll
    for (int off = 16; off; off >>= 1) {
        u64 o = __shfl_xor_sync(0xffffffffu, v, off);
        if (o > v) v = o;
    }
    return v;
}

// ---------------------------------------------------------------------------
// Kernel 1: sigmoid + transpose logits [b][n][c] -> scores_t [b][c][n]
// ---------------------------------------------------------------------------
__global__ void sig_transpose_kernel(const float* __restrict__ logits) {
    __shared__ float tile[32][33];
    int b = blockIdx.z;
    int n0 = blockIdx.x * 32, c0 = blockIdx.y * 32;
    int tx = threadIdx.x, ty = threadIdx.y;
#pragma unroll
    for (int i = 0; i < 4; i++) {
        int c = c0 + tx;
        int n = n0 + ty + i * 8;
        float v = 0.f;
        if (c < CC) v = logits[((size_t)b * NP + n) * CC + c];
        tile[ty + i * 8][tx] = 1.f / (1.f + expf(-v));
    }
    __syncthreads();
#pragma unroll
    for (int i = 0; i < 4; i++) {
        int n = n0 + tx;
        int c = c0 + ty + i * 8;
        if (c < CC) g_scores_t[((size_t)b * CC + c) * NP + n] = tile[tx][ty + i * 8];
    }
}

// ---------------------------------------------------------------------------
// Kernel 2: block-per-(b,g), 8 warps x 500 preds. Batched compute phase with
// per-lane top-4 register caches; per-warp top-13 via 13 warp-max pops (with
// cooperative refill); warp 0 merges 8x13=104 candidates -> global top-13 and
// scatters via atomicMax. One __syncthreads total.
// ---------------------------------------------------------------------------
__global__ void __launch_bounds__(TPB, 3) assign_kernel(
    const float4* __restrict__ pred_boxes,
    const float4* __restrict__ gt_boxes,
    const int* __restrict__ gt_labels)
{
    __shared__ u64 s_cand[NW * KTOP];   // 104 candidates
    __shared__ int s_cons[NW][KTOP];    // per-warp consumed pred indices

    int tid = threadIdx.x;
    int wid = tid >> 5, lane = tid & 31;
    int p = blockIdx.x;                 // (b,g) pair id
    int b = p / GG;
    int g = p - b * GG;

    Box gb = toxyxy(gt_boxes[b * GG + g]);
    int label = gt_labels[b * GG + g];
    const float*  srow = g_scores_t + ((size_t)b * CC + label) * NP;
    const float4* pb   = pred_boxes + (size_t)b * NP;
    int base = wid * NPW;

    if (lane < KTOP) s_cons[wid][lane] = -1;

    // ---- compute phase: batched (4 independent alignments, then inserts) ----
    u64 k1 = 0ull, k2 = 0ull, k3 = 0ull, k4 = 0ull;
    u32 m4 = 0u;

    for (int jb = 0; jb < JMAX; jb += 4) {
        u32 mv[4]; int nn[4]; bool vd[4];
#pragma unroll
        for (int t = 0; t < 4; t++) {
            int nl = lane + (jb + t) * 32;
            vd[t] = nl < NPW;
            int n = base + (vd[t] ? nl : 0);
            nn[t] = n;
            Box pbox = toxyxy(__ldg(&pb[n]));
            float ov = neg_giou(pbox, gb);
            float al = __ldg(srow + n) * pow6(ov);
            mv[t] = fmap(al);
        }
#pragma unroll
        for (int t = 0; t < 4; t++) {
            if (vd[t] && mv[t] >= m4) {
                u64 key = ((u64)mv[t] << 32)
                        | (u64)(0xffffffffu - (u32)nn[t]);
                if (key > k4) {
                    if (key > k3) {
                        k4 = k3;
                        if (key > k2) { k3 = k2; if (key > k1) { k2 = k1; k1 = key; } else k2 = key; }
                        else k3 = key;
                    } else k4 = key;
                    m4 = (u32)(k4 >> 32);
                }
            }
        }
    }
    __syncwarp();

    // ---- per-warp selection: 13 pops, barrier-free within the warp ----
    for (int k = 0; k < KTOP; k++) {
        u64 w = warp_max64(k1);
        if (lane == 0) s_cand[wid * KTOP + k] = w;
        bool owner = (w != 0ull) && (k1 == w);
        if (owner) {
            s_cons[wid][k] = (int)(0xffffffffu - (u32)w);
            k1 = k2; k2 = k3; k3 = k4; k4 = 0ull;
        }
        __syncwarp();

        if (k < KTOP - 1) {
            unsigned need = __ballot_sync(0xffffffffu, owner && k1 == 0ull);
            if (need) {
                int ol = __ffs((int)need) - 1;   // exhausted owner lane
                u64 best = 0ull;
                int nl = ol + lane * 32;         // lane covers owner's j=lane
                if (nl < NPW) {
                    int n = base + nl;
                    bool cons = false;
                    for (int t = 0; t <= k; t++)
                        if (s_cons[wid][t] == n) cons = true;
                    if (!cons) {
                        Box pbox = toxyxy(__ldg(&pb[n]));
                        float ov = neg_giou(pbox, gb);
                        float al = __ldg(srow + n) * pow6(ov);
                        best = pack_key(al, (u32)n);
                    }
                }
                best = warp_max64(best);
                if (lane == ol) k1 = best;
            }
        }
    }
    __syncthreads();

    // ---- merge: warp 0 reduces 104 candidates -> top-13, scatters ----
    if (wid == 0) {
        u64 c0 = s_cand[lane];
        u64 c1 = s_cand[lane + 32];
        u64 c2 = s_cand[lane + 64];
        u64 c3 = (lane + 96 < NW * KTOP) ? s_cand[lane + 96] : 0ull;
        u64* keyb = g_key + (size_t)b * NP;

        for (int k = 0; k < KTOP; k++) {
            u64 m = c0;
            if (c1 > m) m = c1;
            if (c2 > m) m = c2;
            if (c3 > m) m = c3;
            u64 w = warp_max64(m);
            if ((u32)(w >> 32) <= 0x80000000u) break;   // best alignment <= 0

            bool own = (c0 == w) || (c1 == w) || (c2 == w) || (c3 == w);
            unsigned bal = __ballot_sync(0xffffffffu, own);
            if (lane == __ffs((int)bal) - 1) {
                if (c0 == w) c0 = 0ull;
                else if (c1 == w) c1 = 0ull;
                else if (c2 == w) c2 = 0ull;
                else c3 = 0ull;
                int n = (int)(0xffffffffu - (u32)w);
                Box pbox = toxyxy(__ldg(&pb[n]));
                float ov = neg_giou(pbox, gb);
                atomicMax(keyb + n, pack_key(ov, (u32)g));
            }
        }
    }
}

// ---------------------------------------------------------------------------
// Kernel 3: finalize — decode winner from key (ov is embedded), reset key.
// ---------------------------------------------------------------------------
__global__ void finalize_kernel(
    const int* __restrict__ gt_labels,
    float* __restrict__ out)
{
    int i = blockIdx.x * blockDim.x + threadIdx.x;
    if (i >= BS * NP) return;
    int b = i / NP;
    int n = i - b * NP;

    u64 key = g_key[i];
    g_key[i] = 0ull;    // reset for next graph replay
    float inds = 0.f, lab = -1.f, met = 0.f;
    if (key != 0ull) {
        int g = (int)(0xffffffffu - (u32)(key & 0xffffffffu));
        float ov = fmap_inv((u32)(key >> 32));
        int label = gt_labels[b * GG + g];
        float s = g_scores_t[((size_t)b * CC + label) * NP + n];
        met = s * pow6(ov);
        inds = (float)(g + 1);
        lab = (float)label;
    }
    out[i] = inds;
    out[BS * NP + i] = lab;
    out[2 * BS * NP + i] = met;
}

// ---------------------------------------------------------------------------
extern "C" void kernel_launch(void* const* d_in, const int* in_sizes, int n_in,
                              void* d_out, int out_size) {
    const float*  logits     = (const float*)d_in[0];
    const float4* pred_boxes = (const float4*)d_in[1];
    const float4* gt_boxes   = (const float4*)d_in[2];
    const int*    gt_labels  = (const int*)d_in[3];
    float* out = (float*)d_out;

    dim3 tgrid(NP / 32, (CC + 31) / 32, BS);
    sig_transpose_kernel<<<tgrid, dim3(32, 8)>>>(logits);
    assign_kernel<<<BS * GG, TPB>>>(pred_boxes, gt_boxes, gt_labels);
    finalize_kernel<<<(BS * NP + 255) / 256, 256>>>(gt_labels, out);
}

// round 11
// speedup vs baseline: 1.8324x; 1.8324x over previous
#include <cuda_runtime.h>
#include <math.h>

#define BS   16
#define NP   4000
#define CC   80
#define GG   300
#define KTOP 13
#define KPOP 16           // approx candidates collected per GT (margin over 13)
#define WPB  8            // warps per block in assign
#define JPT  125          // elements per lane (32*125 = 4000)

typedef unsigned long long u64;
typedef unsigned int u32;

// Scratch (device globals; zero-initialized at load)
__device__ float  g_scores_t[BS * CC * NP];  // sigmoid(logits) transposed [b][c][n]
__device__ u64    g_key[BS * NP];            // packed (mapped_overlap, ~g) per pred
__device__ float4 g_pxyxy[BS * NP];          // pred boxes converted to xyxy
__device__ float  g_parea[BS * NP];          // pred box areas

struct Box { float x1, y1, x2, y2, area; };

__device__ __forceinline__ Box toxyxy(float4 b) {
    Box r;
    r.x1 = b.x - 0.5f * b.z;
    r.y1 = b.y - 0.5f * b.w;
    r.x2 = b.x + 0.5f * b.z;
    r.y2 = b.y + 0.5f * b.w;
    r.area = (r.x2 - r.x1) * (r.y2 - r.y1);
    return r;
}

// EXACT mirror of the reference arithmetic (order of ops matters for ranking)
__device__ __forceinline__ float exact_neg_giou(float4 p, float pa, const Box& b) {
    float ltx = fmaxf(p.x, b.x1), lty = fmaxf(p.y, b.y1);
    float rbx = fminf(p.z, b.x2), rby = fminf(p.w, b.y2);
    float wi = fmaxf(rbx - ltx, 0.f), hi = fmaxf(rby - lty, 0.f);
    float inter = wi * hi;
    float uni = pa + b.area - inter;
    float iou = inter / uni;
    float lex = fminf(p.x, b.x1), ley = fminf(p.y, b.y1);
    float rex = fmaxf(p.z, b.x2), rey = fmaxf(p.w, b.y2);
    float we = fmaxf(rex - lex, 0.f), he = fmaxf(rey - ley, 0.f);
    float ae = we * he;
    float giou = iou - (ae - uni) / ae;
    return -giou;
}

// APPROX (screening only): single fast division, combined formula.
// -giou = 1 - (inter*ae + uni^2) / (uni*ae); enclosing wh >= 0 geometrically.
__device__ __forceinline__ float approx_neg_giou(float4 p, float pa, const Box& b) {
    float ltx = fmaxf(p.x, b.x1), lty = fmaxf(p.y, b.y1);
    float rbx = fminf(p.z, b.x2), rby = fminf(p.w, b.y2);
    float wi = fmaxf(rbx - ltx, 0.f), hi = fmaxf(rby - lty, 0.f);
    float inter = wi * hi;
    float uni = pa + b.area - inter;
    float lex = fminf(p.x, b.x1), ley = fminf(p.y, b.y1);
    float rex = fmaxf(p.z, b.x2), rey = fmaxf(p.w, b.y2);
    float ae = (rex - lex) * (rey - ley);
    return 1.f - __fdividef(inter * ae + uni * uni, uni * ae);
}

__device__ __forceinline__ float pow6(float x) {
    float x2 = x * x;
    return x2 * x2 * x2;
}

// monotone map float -> u32 (order-preserving as unsigned), and inverse
__device__ __forceinline__ u32 fmap(float f) {
    u32 u = __float_as_uint(f);
    return (u & 0x80000000u) ? ~u : (u | 0x80000000u);
}
__device__ __forceinline__ float fmap_inv(u32 m) {
    u32 u = (m & 0x80000000u) ? (m & 0x7fffffffu) : ~m;
    return __uint_as_float(u);
}
__device__ __forceinline__ u64 pack_key(float v, u32 idx) {
    return ((u64)fmap(v) << 32) | (u64)(0xffffffffu - idx);
}
// for values known >= 0 (alignments): single-OR monotone map
__device__ __forceinline__ u64 pack_key_pos(float v, u32 idx) {
    return ((u64)(__float_as_uint(v) | 0x80000000u) << 32) | (u64)(0xffffffffu - idx);
}

__device__ __forceinline__ u64 warp_max64(u64 v) {
#pragma unroll
    for (int off = 16; off; off >>= 1) {
        u64 o = __shfl_xor_sync(0xffffffffu, v, off);
        if (o > v) v = o;
    }
    return v;
}

// ---------------------------------------------------------------------------
// Kernel 0: convert pred boxes to xyxy + area (once per replay)
// ---------------------------------------------------------------------------
__global__ void boxprep_kernel(const float4* __restrict__ pred_boxes) {
    int i = blockIdx.x * blockDim.x + threadIdx.x;
    if (i < BS * NP) {
        float4 b = pred_boxes[i];
        float x1 = b.x - 0.5f * b.z, y1 = b.y - 0.5f * b.w;
        float x2 = b.x + 0.5f * b.z, y2 = b.y + 0.5f * b.w;
        g_pxyxy[i] = make_float4(x1, y1, x2, y2);
        g_parea[i] = (x2 - x1) * (y2 - y1);
    }
}

// ---------------------------------------------------------------------------
// Kernel 1: sigmoid + transpose logits [b][n][c] -> scores_t [b][c][n]
// ---------------------------------------------------------------------------
__global__ void sig_transpose_kernel(const float* __restrict__ logits) {
    __shared__ float tile[32][33];
    int b = blockIdx.z;
    int n0 = blockIdx.x * 32, c0 = blockIdx.y * 32;
    int tx = threadIdx.x, ty = threadIdx.y;
#pragma unroll
    for (int i = 0; i < 4; i++) {
        int c = c0 + tx;
        int n = n0 + ty + i * 8;
        float v = 0.f;
        if (c < CC) v = logits[((size_t)b * NP + n) * CC + c];
        tile[ty + i * 8][tx] = 1.f / (1.f + expf(-v));
    }
    __syncthreads();
#pragma unroll
    for (int i = 0; i < 4; i++) {
        int n = n0 + tx;
        int c = c0 + ty + i * 8;
        if (c < CC) g_scores_t[((size_t)b * CC + c) * NP + n] = tile[tx][ty + i * 8];
    }
}

// ---------------------------------------------------------------------------
// Kernel 2: warp-per-(b,g). Pass 1: approx alignment (1 fast div), per-lane
// top-4 caches + refill -> approx top-16 candidates. Pass 2: exact reference
// arithmetic on the 16 candidates; 13 exact pops; scatter exact overlaps.
// ---------------------------------------------------------------------------
__global__ void __launch_bounds__(WPB * 32) assign_kernel(
    const float4* __restrict__ gt_boxes,
    const int* __restrict__ gt_labels)
{
    __shared__ int s_cons[WPB][KPOP];   // popped candidate pred indices

    int wid  = threadIdx.x >> 5;
    int lane = threadIdx.x & 31;
    int p = blockIdx.x * WPB + wid;     // (b,g) pair id, 0..4799
    int b = p / GG;
    int g = p - b * GG;

    Box gbb = toxyxy(gt_boxes[b * GG + g]);
    int label = gt_labels[b * GG + g];
    const float*  srow = g_scores_t + ((size_t)b * CC + label) * NP;
    const float4* pxy  = g_pxyxy + (size_t)b * NP;
    const float*  par  = g_parea + (size_t)b * NP;

    // ---- pass 1: stream 125 elements/lane, approx values, sorted top-4 ----
    u64 k1 = 0ull, k2 = 0ull, k3 = 0ull, k4 = 0ull;
    u32 m4 = 0u;

#pragma unroll 5
    for (int j = 0; j < JPT; j++) {
        int n = lane + j * 32;
        float ov = approx_neg_giou(pxy[n], par[n], gbb);
        float al = srow[n] * pow6(ov);          // >= 0 always
        u32 ma = __float_as_uint(al) | 0x80000000u;
        if (ma >= m4) {
            u64 key = ((u64)ma << 32) | (u64)(0xffffffffu - (u32)n);
            if (key > k4) {
                if (key > k3) {
                    k4 = k3;
                    if (key > k2) { k3 = k2; if (key > k1) { k2 = k1; k1 = key; } else k2 = key; }
                    else k3 = key;
                } else k4 = key;
                m4 = (u32)(k4 >> 32);
            }
        }
    }

    // ---- collect approx top-16 (pops + cooperative refill) ----
    int cnt = 0;
    for (int k = 0; k < KPOP; k++) {
        u64 w = warp_max64(k1);
        if ((u32)(w >> 32) == 0u) break;        // caches empty (never in practice)
        bool owner = (k1 == w);
        if (owner) {
            s_cons[wid][k] = (int)(0xffffffffu - (u32)w);
            k1 = k2; k2 = k3; k3 = k4; k4 = 0ull;
        }
        cnt++;
        __syncwarp();

        if (k < KPOP - 1) {
            unsigned need = __ballot_sync(0xffffffffu, owner && k1 == 0ull);
            if (need) {
                int ol = __ffs((int)need) - 1;  // exhausted owner lane
                u64 best = 0ull;
#pragma unroll
                for (int m = 0; m < 4; m++) {
                    int j = lane + m * 32;
                    if (j < JPT) {
                        int n = ol + j * 32;
                        bool cons = false;
                        for (int t = 0; t <= k; t++)
                            if (s_cons[wid][t] == n) cons = true;
                        if (!cons) {
                            float ov = approx_neg_giou(pxy[n], par[n], gbb);
                            float al = srow[n] * pow6(ov);
                            u64 key = pack_key_pos(al, (u32)n);
                            if (key > best) best = key;
                        }
                    }
                }
                best = warp_max64(best);
                if (lane == ol) k1 = best;
            }
        }
    }
    __syncwarp();

    // ---- pass 2: exact evaluation of candidates, 13 exact pops, scatter ----
    int myn = (lane < cnt) ? s_cons[wid][lane] : -1;
    u64 ekey = 0ull;
    float eov = 0.f;
    if (myn >= 0) {
        eov = exact_neg_giou(pxy[myn], par[myn], gbb);
        float eal = srow[myn] * pow6(eov);
        ekey = pack_key_pos(eal, (u32)myn);
    }

    u64* keyb = g_key + (size_t)b * NP;
    for (int k = 0; k < KTOP; k++) {
        u64 w = warp_max64(ekey);
        if ((u32)(w >> 32) <= 0x80000000u) break;   // best alignment <= 0
        if (ekey == w) {
            ekey = 0ull;
            atomicMax(keyb + myn, pack_key(eov, (u32)g));
        }
    }
}

// ---------------------------------------------------------------------------
// Kernel 3: finalize — decode winner from key (ov is embedded), reset key.
// ---------------------------------------------------------------------------
__global__ void finalize_kernel(
    const int* __restrict__ gt_labels,
    float* __restrict__ out)
{
    int i = blockIdx.x * blockDim.x + threadIdx.x;
    if (i >= BS * NP) return;
    int b = i / NP;
    int n = i - b * NP;

    u64 key = g_key[i];
    g_key[i] = 0ull;    // reset for next graph replay
    float inds = 0.f, lab = -1.f, met = 0.f;
    if (key != 0ull) {
        int g = (int)(0xffffffffu - (u32)(key & 0xffffffffu));
        float ov = fmap_inv((u32)(key >> 32));
        int label = gt_labels[b * GG + g];
        float s = g_scores_t[((size_t)b * CC + label) * NP + n];
        met = s * pow6(ov);
        inds = (float)(g + 1);
        lab = (float)label;
    }
    out[i] = inds;
    out[BS * NP + i] = lab;
    out[2 * BS * NP + i] = met;
}

// ---------------------------------------------------------------------------
extern "C" void kernel_launch(void* const* d_in, const int* in_sizes, int n_in,
                              void* d_out, int out_size) {
    const float*  logits     = (const float*)d_in[0];
    const float4* pred_boxes = (const float4*)d_in[1];
    const float4* gt_boxes   = (const float4*)d_in[2];
    const int*    gt_labels  = (const int*)d_in[3];
    float* out = (float*)d_out;

    boxprep_kernel<<<(BS * NP + 255) / 256, 256>>>(pred_boxes);
    dim3 tgrid(NP / 32, (CC + 31) / 32, BS);
    sig_transpose_kernel<<<tgrid, dim3(32, 8)>>>(logits);
    assign_kernel<<<(BS * GG) / WPB, WPB * 32>>>(gt_boxes, gt_labels);
    finalize_kernel<<<(BS * NP + 255) / 256, 256>>>(gt_labels, out);
}

// round 12
// speedup vs baseline: 1.8497x; 1.0094x over previous
#include <cuda_runtime.h>
#include <math.h>

#define BS   16
#define NP   4000
#define CC   80
#define GG   300
#define KTOP 13
#define KPOP 16           // approx candidates collected per GT (margin over 13)
#define WPB  10           // warps per assign block (divides GG=300)
#define JPT  125          // elements per lane (32*125 = 4000)
#define TILE 800          // preds per smem tile (32*25); 5 tiles = 4000
#define JT   25           // iters per lane per tile

typedef unsigned long long u64;
typedef unsigned int u32;

// Scratch (device globals; zero-initialized at load)
__device__ float  g_scores_t[BS * CC * NP];  // sigmoid(logits) transposed [b][c][n]
__device__ u64    g_key[BS * NP];            // packed (mapped_overlap, ~g) per pred
__device__ float4 g_pxyxy[BS * NP];          // pred boxes converted to xyxy
__device__ float  g_parea[BS * NP];          // pred box areas

struct Box { float x1, y1, x2, y2, area; };

__device__ __forceinline__ Box toxyxy(float4 b) {
    Box r;
    r.x1 = b.x - 0.5f * b.z;
    r.y1 = b.y - 0.5f * b.w;
    r.x2 = b.x + 0.5f * b.z;
    r.y2 = b.y + 0.5f * b.w;
    r.area = (r.x2 - r.x1) * (r.y2 - r.y1);
    return r;
}

// EXACT mirror of the reference arithmetic (order of ops matters for ranking)
__device__ __forceinline__ float exact_neg_giou(float4 p, float pa, const Box& b) {
    float ltx = fmaxf(p.x, b.x1), lty = fmaxf(p.y, b.y1);
    float rbx = fminf(p.z, b.x2), rby = fminf(p.w, b.y2);
    float wi = fmaxf(rbx - ltx, 0.f), hi = fmaxf(rby - lty, 0.f);
    float inter = wi * hi;
    float uni = pa + b.area - inter;
    float iou = inter / uni;
    float lex = fminf(p.x, b.x1), ley = fminf(p.y, b.y1);
    float rex = fmaxf(p.z, b.x2), rey = fmaxf(p.w, b.y2);
    float we = fmaxf(rex - lex, 0.f), he = fmaxf(rey - ley, 0.f);
    float ae = we * he;
    float giou = iou - (ae - uni) / ae;
    return -giou;
}

// APPROX (screening only): single fast division, combined formula.
__device__ __forceinline__ float approx_neg_giou(float4 p, float pa, const Box& b) {
    float ltx = fmaxf(p.x, b.x1), lty = fmaxf(p.y, b.y1);
    float rbx = fminf(p.z, b.x2), rby = fminf(p.w, b.y2);
    float wi = fmaxf(rbx - ltx, 0.f), hi = fmaxf(rby - lty, 0.f);
    float inter = wi * hi;
    float uni = pa + b.area - inter;
    float lex = fminf(p.x, b.x1), ley = fminf(p.y, b.y1);
    float rex = fmaxf(p.z, b.x2), rey = fmaxf(p.w, b.y2);
    float ae = (rex - lex) * (rey - ley);
    return 1.f - __fdividef(inter * ae + uni * uni, uni * ae);
}

__device__ __forceinline__ float pow6(float x) {
    float x2 = x * x;
    return x2 * x2 * x2;
}

__device__ __forceinline__ u32 fmap(float f) {
    u32 u = __float_as_uint(f);
    return (u & 0x80000000u) ? ~u : (u | 0x80000000u);
}
__device__ __forceinline__ float fmap_inv(u32 m) {
    u32 u = (m & 0x80000000u) ? (m & 0x7fffffffu) : ~m;
    return __uint_as_float(u);
}
__device__ __forceinline__ u64 pack_key(float v, u32 idx) {
    return ((u64)fmap(v) << 32) | (u64)(0xffffffffu - idx);
}
// for values known >= 0 (alignments): single-OR monotone map
__device__ __forceinline__ u64 pack_key_pos(float v, u32 idx) {
    return ((u64)(__float_as_uint(v) | 0x80000000u) << 32) | (u64)(0xffffffffu - idx);
}

__device__ __forceinline__ u64 warp_max64(u64 v) {
#pragma unroll
    for (int off = 16; off; off >>= 1) {
        u64 o = __shfl_xor_sync(0xffffffffu, v, off);
        if (o > v) v = o;
    }
    return v;
}

// ---------------------------------------------------------------------------
// Kernel 1: fused prep. y<3: sigmoid+transpose tile; y==3: boxprep slice.
// grid (125, 4, 16), block (32, 8)
// ---------------------------------------------------------------------------
__global__ void prep_kernel(const float* __restrict__ logits,
                            const float4* __restrict__ pred_boxes) {
    int b = blockIdx.z;
    if (blockIdx.y == 3) {
        int tid = threadIdx.y * 32 + threadIdx.x;
        if (tid < 32) {
            int n = blockIdx.x * 32 + tid;
            int i = b * NP + n;
            float4 v = pred_boxes[i];
            float x1 = v.x - 0.5f * v.z, y1 = v.y - 0.5f * v.w;
            float x2 = v.x + 0.5f * v.z, y2 = v.y + 0.5f * v.w;
            g_pxyxy[i] = make_float4(x1, y1, x2, y2);
            g_parea[i] = (x2 - x1) * (y2 - y1);
        }
        return;
    }
    __shared__ float tile[32][33];
    int n0 = blockIdx.x * 32, c0 = blockIdx.y * 32;
    int tx = threadIdx.x, ty = threadIdx.y;
#pragma unroll
    for (int i = 0; i < 4; i++) {
        int c = c0 + tx;
        int n = n0 + ty + i * 8;
        float v = 0.f;
        if (c < CC) v = logits[((size_t)b * NP + n) * CC + c];
        tile[ty + i * 8][tx] = 1.f / (1.f + expf(-v));
    }
    __syncthreads();
#pragma unroll
    for (int i = 0; i < 4; i++) {
        int n = n0 + tx;
        int c = c0 + ty + i * 8;
        if (c < CC) g_scores_t[((size_t)b * CC + c) * NP + n] = tile[tx][ty + i * 8];
    }
}

// ---------------------------------------------------------------------------
// Kernel 2: 10 warps per block, all same batch b. Pred boxes staged in smem
// tiles of 800, loaded once per block. Pass 1 approx screen -> top-16;
// pass 2 exact verify + 13 pops + scatter. Refill recomputes from gmem.
// ---------------------------------------------------------------------------
__global__ void __launch_bounds__(WPB * 32) assign_kernel(
    const float4* __restrict__ gt_boxes,
    const int* __restrict__ gt_labels)
{
    __shared__ float4 s_box[TILE];
    __shared__ float  s_area[TILE];
    __shared__ int    s_cons[WPB][KPOP];

    int tid  = threadIdx.x;
    int wid  = tid >> 5;
    int lane = tid & 31;
    int p = blockIdx.x * WPB + wid;     // (b,g) pair id; same b for whole block
    int b = p / GG;
    int g = p - b * GG;

    Box gbb = toxyxy(gt_boxes[b * GG + g]);
    int label = gt_labels[b * GG + g];
    const float*  srow = g_scores_t + ((size_t)b * CC + label) * NP;
    const float4* pxy  = g_pxyxy + (size_t)b * NP;
    const float*  par  = g_parea + (size_t)b * NP;

    // ---- pass 1: tiles staged in smem; per-lane sorted top-4 in registers ----
    u64 k1 = 0ull, k2 = 0ull, k3 = 0ull, k4 = 0ull;
    u32 m4 = 0u;

    for (int t = 0; t < NP / TILE; t++) {
        __syncthreads();    // previous tile fully consumed
        for (int i = tid; i < TILE; i += WPB * 32) {
            s_box[i]  = pxy[t * TILE + i];
            s_area[i] = par[t * TILE + i];
        }
        __syncthreads();

#pragma unroll 5
        for (int j = 0; j < JT; j++) {
            int nl = lane + j * 32;
            int n  = t * TILE + nl;
            float ov = approx_neg_giou(s_box[nl], s_area[nl], gbb);
            float al = __ldg(srow + n) * pow6(ov);      // >= 0 always
            u32 ma = __float_as_uint(al) | 0x80000000u;
            if (ma >= m4) {
                u64 key = ((u64)ma << 32) | (u64)(0xffffffffu - (u32)n);
                if (key > k4) {
                    if (key > k3) {
                        k4 = k3;
                        if (key > k2) { k3 = k2; if (key > k1) { k2 = k1; k1 = key; } else k2 = key; }
                        else k3 = key;
                    } else k4 = key;
                    m4 = (u32)(k4 >> 32);
                }
            }
        }
    }

    // ---- collect approx top-16 (pops + cooperative refill from gmem) ----
    int cnt = 0;
    for (int k = 0; k < KPOP; k++) {
        u64 w = warp_max64(k1);
        if ((u32)(w >> 32) == 0u) break;    // caches empty
        bool owner = (k1 == w);
        if (owner) {
            s_cons[wid][k] = (int)(0xffffffffu - (u32)w);
            k1 = k2; k2 = k3; k3 = k4; k4 = 0ull;
        }
        cnt++;
        __syncwarp();

        if (k < KPOP - 1) {
            unsigned need = __ballot_sync(0xffffffffu, owner && k1 == 0ull);
            if (need) {
                int ol = __ffs((int)need) - 1;  // exhausted owner lane
                u64 best = 0ull;
#pragma unroll
                for (int m = 0; m < 4; m++) {
                    int j = lane + m * 32;
                    if (j < JPT) {
                        int n = ol + j * 32;    // owner's global stride-32 set
                        bool cons = false;
                        for (int t2 = 0; t2 <= k; t2++)
                            if (s_cons[wid][t2] == n) cons = true;
                        if (!cons) {
                            float ov = approx_neg_giou(__ldg(&pxy[n]), __ldg(&par[n]), gbb);
                            float al = __ldg(srow + n) * pow6(ov);
                            u64 key = pack_key_pos(al, (u32)n);
                            if (key > best) best = key;
                        }
                    }
                }
                best = warp_max64(best);
                if (lane == ol) k1 = best;
            }
        }
    }
    __syncwarp();

    // ---- pass 2: exact evaluation of candidates, 13 exact pops, scatter ----
    int myn = (lane < cnt) ? s_cons[wid][lane] : -1;
    u64 ekey = 0ull;
    float eov = 0.f;
    if (myn >= 0) {
        eov = exact_neg_giou(__ldg(&pxy[myn]), __ldg(&par[myn]), gbb);
        float eal = __ldg(srow + myn) * pow6(eov);
        ekey = pack_key_pos(eal, (u32)myn);
    }

    u64* keyb = g_key + (size_t)b * NP;
    for (int k = 0; k < KTOP; k++) {
        u64 w = warp_max64(ekey);
        if ((u32)(w >> 32) <= 0x80000000u) break;   // best alignment <= 0
        if (ekey == w) {
            ekey = 0ull;
            atomicMax(keyb + myn, pack_key(eov, (u32)g));
        }
    }
}

// ---------------------------------------------------------------------------
// Kernel 3: finalize — decode winner from key (ov is embedded), reset key.
// ---------------------------------------------------------------------------
__global__ void finalize_kernel(
    const int* __restrict__ gt_labels,
    float* __restrict__ out)
{
    int i = blockIdx.x * blockDim.x + threadIdx.x;
    if (i >= BS * NP) return;
    int b = i / NP;
    int n = i - b * NP;

    u64 key = g_key[i];
    g_key[i] = 0ull;    // reset for next graph replay
    float inds = 0.f, lab = -1.f, met = 0.f;
    if (key != 0ull) {
        int g = (int)(0xffffffffu - (u32)(key & 0xffffffffu));
        float ov = fmap_inv((u32)(key >> 32));
        int label = __ldg(gt_labels + b * GG + g);
        float s = g_scores_t[((size_t)b * CC + label) * NP + n];
        met = s * pow6(ov);
        inds = (float)(g + 1);
        lab = (float)label;
    }
    out[i] = inds;
    out[BS * NP + i] = lab;
    out[2 * BS * NP + i] = met;
}

// ---------------------------------------------------------------------------
extern "C" void kernel_launch(void* const* d_in, const int* in_sizes, int n_in,
                              void* d_out, int out_size) {
    const float*  logits     = (const float*)d_in[0];
    const float4* pred_boxes = (const float4*)d_in[1];
    const float4* gt_boxes   = (const float4*)d_in[2];
    const int*    gt_labels  = (const int*)d_in[3];
    float* out = (float*)d_out;

    dim3 pgrid(NP / 32, 4, BS);
    prep_kernel<<<pgrid, dim3(32, 8)>>>(logits, pred_boxes);
    assign_kernel<<<(BS * GG) / WPB, WPB * 32>>>(gt_boxes, gt_labels);
    finalize_kernel<<<(BS * NP + 127) / 128, 128>>>(gt_labels, out);
}

// round 13
// speedup vs baseline: 2.5412x; 1.3739x over previous
#include <cuda_runtime.h>
#include <math.h>

#define BS   16
#define NP   4000
#define CC   80
#define GG   300
#define KTOP 13
#define KPOP 16           // approx candidates collected per GT (margin over 13)
#define WPB  8            // warps per block in assign
#define JPT  125          // elements per lane (32*125 = 4000)

typedef unsigned long long u64;
typedef unsigned int u32;

// Scratch (device globals; zero-initialized at load)
__device__ float  g_scores_t[BS * CC * NP];  // sigmoid(logits) transposed [b][c][n]
__device__ u64    g_key[BS * NP];            // packed (mapped_overlap, ~g) per pred
__device__ float4 g_pxyxy[BS * NP];          // pred boxes converted to xyxy
__device__ float  g_parea[BS * NP];          // pred box areas

struct Box { float x1, y1, x2, y2, area; };

__device__ __forceinline__ Box toxyxy(float4 b) {
    Box r;
    r.x1 = b.x - 0.5f * b.z;
    r.y1 = b.y - 0.5f * b.w;
    r.x2 = b.x + 0.5f * b.z;
    r.y2 = b.y + 0.5f * b.w;
    r.area = (r.x2 - r.x1) * (r.y2 - r.y1);
    return r;
}

// EXACT mirror of the reference arithmetic (order of ops matters for ranking)
__device__ __forceinline__ float exact_neg_giou(float4 p, float pa, const Box& b) {
    float ltx = fmaxf(p.x, b.x1), lty = fmaxf(p.y, b.y1);
    float rbx = fminf(p.z, b.x2), rby = fminf(p.w, b.y2);
    float wi = fmaxf(rbx - ltx, 0.f), hi = fmaxf(rby - lty, 0.f);
    float inter = wi * hi;
    float uni = pa + b.area - inter;
    float iou = inter / uni;
    float lex = fminf(p.x, b.x1), ley = fminf(p.y, b.y1);
    float rex = fmaxf(p.z, b.x2), rey = fmaxf(p.w, b.y2);
    float we = fmaxf(rex - lex, 0.f), he = fmaxf(rey - ley, 0.f);
    float ae = we * he;
    float giou = iou - (ae - uni) / ae;
    return -giou;
}

// APPROX (screening only): single fast division, combined formula.
__device__ __forceinline__ float approx_neg_giou(float4 p, float pa, const Box& b) {
    float ltx = fmaxf(p.x, b.x1), lty = fmaxf(p.y, b.y1);
    float rbx = fminf(p.z, b.x2), rby = fminf(p.w, b.y2);
    float wi = fmaxf(rbx - ltx, 0.f), hi = fmaxf(rby - lty, 0.f);
    float inter = wi * hi;
    float uni = pa + b.area - inter;
    float lex = fminf(p.x, b.x1), ley = fminf(p.y, b.y1);
    float rex = fmaxf(p.z, b.x2), rey = fmaxf(p.w, b.y2);
    float ae = (rex - lex) * (rey - ley);
    return 1.f - __fdividef(inter * ae + uni * uni, uni * ae);
}

__device__ __forceinline__ float pow6(float x) {
    float x2 = x * x;
    return x2 * x2 * x2;
}

__device__ __forceinline__ u32 fmap(float f) {
    u32 u = __float_as_uint(f);
    return (u & 0x80000000u) ? ~u : (u | 0x80000000u);
}
__device__ __forceinline__ float fmap_inv(u32 m) {
    u32 u = (m & 0x80000000u) ? (m & 0x7fffffffu) : ~m;
    return __uint_as_float(u);
}
__device__ __forceinline__ u64 pack_key(float v, u32 idx) {
    return ((u64)fmap(v) << 32) | (u64)(0xffffffffu - idx);
}
// for values known >= 0 (alignments): single-OR monotone map
__device__ __forceinline__ u64 pack_key_pos(float v, u32 idx) {
    return ((u64)(__float_as_uint(v) | 0x80000000u) << 32) | (u64)(0xffffffffu - idx);
}

__device__ __forceinline__ u64 warp_max64(u64 v) {
#pragma unroll
    for (int off = 16; off; off >>= 1) {
        u64 o = __shfl_xor_sync(0xffffffffu, v, off);
        if (o > v) v = o;
    }
    return v;
}

// ---------------------------------------------------------------------------
// Kernel 1: fused prep. y<3: sigmoid+transpose tile; y==3: boxprep slice.
// grid (125, 4, 16), block (32, 8)
// ---------------------------------------------------------------------------
__global__ void prep_kernel(const float* __restrict__ logits,
                            const float4* __restrict__ pred_boxes) {
    int b = blockIdx.z;
    if (blockIdx.y == 3) {
        int tid = threadIdx.y * 32 + threadIdx.x;
        if (tid < 32) {
            int n = blockIdx.x * 32 + tid;
            int i = b * NP + n;
            float4 v = pred_boxes[i];
            float x1 = v.x - 0.5f * v.z, y1 = v.y - 0.5f * v.w;
            float x2 = v.x + 0.5f * v.z, y2 = v.y + 0.5f * v.w;
            g_pxyxy[i] = make_float4(x1, y1, x2, y2);
            g_parea[i] = (x2 - x1) * (y2 - y1);
        }
        return;
    }
    __shared__ float tile[32][33];
    int n0 = blockIdx.x * 32, c0 = blockIdx.y * 32;
    int tx = threadIdx.x, ty = threadIdx.y;
#pragma unroll
    for (int i = 0; i < 4; i++) {
        int c = c0 + tx;
        int n = n0 + ty + i * 8;
        float v = 0.f;
        if (c < CC) v = logits[((size_t)b * NP + n) * CC + c];
        tile[ty + i * 8][tx] = 1.f / (1.f + expf(-v));
    }
    __syncthreads();
#pragma unroll
    for (int i = 0; i < 4; i++) {
        int n = n0 + tx;
        int c = c0 + ty + i * 8;
        if (c < CC) g_scores_t[((size_t)b * CC + c) * NP + n] = tile[tx][ty + i * 8];
    }
}

// ---------------------------------------------------------------------------
// Kernel 2: warp-per-(b,g). BRANCHLESS per-lane top-4 (u32 approx value +
// u32 idx, predicated sorted insert). 16 pops via REDUX.UMAX; proven
// cooperative refill when a lane's cache empties. Pass 2 exact verify
// (reference arithmetic, u64 keys with index tie-break) + scatter.
// ---------------------------------------------------------------------------
__global__ void __launch_bounds__(WPB * 32) assign_kernel(
    const float4* __restrict__ gt_boxes,
    const int* __restrict__ gt_labels)
{
    __shared__ int s_cons[WPB][KPOP];   // popped candidate pred indices

    int wid  = threadIdx.x >> 5;
    int lane = threadIdx.x & 31;
    int p = blockIdx.x * WPB + wid;     // (b,g) pair id, 0..4799
    int b = p / GG;
    int g = p - b * GG;

    Box gbb = toxyxy(gt_boxes[b * GG + g]);
    int label = gt_labels[b * GG + g];
    const float*  srow = g_scores_t + ((size_t)b * CC + label) * NP;
    const float4* pxy  = g_pxyxy + (size_t)b * NP;
    const float*  par  = g_parea + (size_t)b * NP;

    // ---- pass 1: branchless per-lane sorted top-4 (value, idx) ----
    u32 m1 = 0u, m2 = 0u, m3 = 0u, m4 = 0u;
    u32 i1 = 0u, i2 = 0u, i3 = 0u, i4 = 0u;

#pragma unroll 5
    for (int j = 0; j < JPT; j++) {
        int n = lane + j * 32;
        float ov = approx_neg_giou(__ldg(&pxy[n]), __ldg(&par[n]), gbb);
        float al = __ldg(srow + n) * pow6(ov);      // >= 0 always
        u32 ma = __float_as_uint(al) | 0x80000000u;
        u32 mi = (u32)n;
        // level 1
        bool c = ma > m1;
        u32 lv = c ? m1 : ma;  u32 li = c ? i1 : mi;
        m1 = c ? ma : m1;      i1 = c ? mi : i1;
        // level 2
        c = lv > m2;
        u32 lv2 = c ? m2 : lv; u32 li2 = c ? i2 : li;
        m2 = c ? lv : m2;      i2 = c ? li : i2;
        // level 3
        c = lv2 > m3;
        u32 lv3 = c ? m3 : lv2; u32 li3 = c ? i3 : li2;
        m3 = c ? lv2 : m3;      i3 = c ? li2 : i3;
        // level 4
        c = lv3 > m4;
        m4 = c ? lv3 : m4;      i4 = c ? li3 : i4;
    }

    // ---- collect approx top-16: pops via REDUX + cooperative refill ----
    int cnt = 0;
    for (int k = 0; k < KPOP; k++) {
        u32 w = __reduce_max_sync(0xffffffffu, m1);
        if (w == 0u) break;                          // all caches empty (never)
        unsigned bal = __ballot_sync(0xffffffffu, m1 == w);
        int owner = __ffs((int)bal) - 1;
        if (lane == owner) {
            s_cons[wid][k] = (int)i1;
            m1 = m2; i1 = i2; m2 = m3; i2 = i3; m3 = m4; i3 = i4; m4 = 0u;
        }
        cnt++;
        __syncwarp();

        if (k < KPOP - 1) {
            unsigned need = __ballot_sync(0xffffffffu,
                                          (lane == owner) && (m1 == 0u));
            if (need) {
                int ol = owner;                     // exhausted owner lane
                u32 bm = 0u, bi = 0u;
#pragma unroll
                for (int m = 0; m < 4; m++) {
                    int j = lane + m * 32;
                    if (j < JPT) {
                        int n = ol + j * 32;        // owner's global stride-32 set
                        bool cons = false;
                        for (int t = 0; t <= k; t++)
                            if (s_cons[wid][t] == n) cons = true;
                        if (!cons) {
                            float ov = approx_neg_giou(__ldg(&pxy[n]), __ldg(&par[n]), gbb);
                            float al = __ldg(srow + n) * pow6(ov);
                            u32 ma = __float_as_uint(al) | 0x80000000u;
                            if (ma > bm) { bm = ma; bi = (u32)n; }
                        }
                    }
                }
#pragma unroll
                for (int off = 16; off; off >>= 1) {
                    u32 om = __shfl_xor_sync(0xffffffffu, bm, off);
                    u32 oi = __shfl_xor_sync(0xffffffffu, bi, off);
                    if (om > bm) { bm = om; bi = oi; }
                }
                if (lane == ol) { m1 = bm; i1 = bi; }
            }
        }
    }
    __syncwarp();

    // ---- pass 2: exact evaluation of candidates, 13 exact pops, scatter ----
    int myn = (lane < cnt) ? s_cons[wid][lane] : -1;
    u64 ekey = 0ull;
    float eov = 0.f;
    if (myn >= 0) {
        eov = exact_neg_giou(__ldg(&pxy[myn]), __ldg(&par[myn]), gbb);
        float eal = __ldg(srow + myn) * pow6(eov);
        ekey = pack_key_pos(eal, (u32)myn);
    }

    u64* keyb = g_key + (size_t)b * NP;
    for (int k = 0; k < KTOP; k++) {
        u64 w = warp_max64(ekey);
        if ((u32)(w >> 32) <= 0x80000000u) break;   // best alignment <= 0
        if (ekey == w) {
            ekey = 0ull;
            atomicMax(keyb + myn, pack_key(eov, (u32)g));
        }
    }
}

// ---------------------------------------------------------------------------
// Kernel 3: finalize — decode winner from key (ov is embedded), reset key.
// ---------------------------------------------------------------------------
__global__ void finalize_kernel(
    const int* __restrict__ gt_labels,
    float* __restrict__ out)
{
    int i = blockIdx.x * blockDim.x + threadIdx.x;
    if (i >= BS * NP) return;
    int b = i / NP;
    int n = i - b * NP;

    u64 key = g_key[i];
    g_key[i] = 0ull;    // reset for next graph replay
    float inds = 0.f, lab = -1.f, met = 0.f;
    if (key != 0ull) {
        int g = (int)(0xffffffffu - (u32)(key & 0xffffffffu));
        float ov = fmap_inv((u32)(key >> 32));
        int label = __ldg(gt_labels + b * GG + g);
        float s = g_scores_t[((size_t)b * CC + label) * NP + n];
        met = s * pow6(ov);
        inds = (float)(g + 1);
        lab = (float)label;
    }
    out[i] = inds;
    out[BS * NP + i] = lab;
    out[2 * BS * NP + i] = met;
}

// ---------------------------------------------------------------------------
extern "C" void kernel_launch(void* const* d_in, const int* in_sizes, int n_in,
                              void* d_out, int out_size) {
    const float*  logits     = (const float*)d_in[0];
    const float4* pred_boxes = (const float4*)d_in[1];
    const float4* gt_boxes   = (const float4*)d_in[2];
    const int*    gt_labels  = (const int*)d_in[3];
    float* out = (float*)d_out;

    dim3 pgrid(NP / 32, 4, BS);
    prep_kernel<<<pgrid, dim3(32, 8)>>>(logits, pred_boxes);
    assign_kernel<<<(BS * GG) / WPB, WPB * 32>>>(gt_boxes, gt_labels);
    finalize_kernel<<<(BS * NP + 127) / 128, 128>>>(gt_labels, out);
}

// round 17
// speedup vs baseline: 2.7589x; 1.0857x over previous
#include <cuda_runtime.h>
#include <math.h>

#define BS   16
#define NP   4000
#define CC   80
#define GG   300
#define KTOP 13
#define KPOP 16           // approx candidates collected per GT (margin over 13)
#define WPB  8            // warps per block in assign
#define JPT  125          // elements per lane (32*125 = 4000)

typedef unsigned long long u64;
typedef unsigned int u32;

// Scratch (device globals; zero-initialized at load)
__device__ float  g_scores_t[BS * CC * NP];  // EXACT sigmoid, transposed [b][c][n]
__device__ u64    g_key[BS * NP];            // packed (mapped_overlap, ~g) per pred
__device__ float4 g_pxyxy[BS * NP];          // pred boxes converted to xyxy
__device__ float  g_parea[BS * NP];          // pred box areas

struct Box { float x1, y1, x2, y2, area; };

__device__ __forceinline__ Box toxyxy(float4 b) {
    Box r;
    r.x1 = b.x - 0.5f * b.z;
    r.y1 = b.y - 0.5f * b.w;
    r.x2 = b.x + 0.5f * b.z;
    r.y2 = b.y + 0.5f * b.w;
    r.area = (r.x2 - r.x1) * (r.y2 - r.y1);
    return r;
}

// EXACT mirror of the reference arithmetic (order of ops matters for ranking)
__device__ __forceinline__ float exact_neg_giou(float4 p, float pa, const Box& b) {
    float ltx = fmaxf(p.x, b.x1), lty = fmaxf(p.y, b.y1);
    float rbx = fminf(p.z, b.x2), rby = fminf(p.w, b.y2);
    float wi = fmaxf(rbx - ltx, 0.f), hi = fmaxf(rby - lty, 0.f);
    float inter = wi * hi;
    float uni = pa + b.area - inter;
    float iou = inter / uni;
    float lex = fminf(p.x, b.x1), ley = fminf(p.y, b.y1);
    float rex = fmaxf(p.z, b.x2), rey = fmaxf(p.w, b.y2);
    float we = fmaxf(rex - lex, 0.f), he = fmaxf(rey - ley, 0.f);
    float ae = we * he;
    float giou = iou - (ae - uni) / ae;
    return -giou;
}

// APPROX (screening only): single fast division, combined formula.
__device__ __forceinline__ float approx_neg_giou(float4 p, float pa, const Box& b) {
    float ltx = fmaxf(p.x, b.x1), lty = fmaxf(p.y, b.y1);
    float rbx = fminf(p.z, b.x2), rby = fminf(p.w, b.y2);
    float wi = fmaxf(rbx - ltx, 0.f), hi = fmaxf(rby - lty, 0.f);
    float inter = wi * hi;
    float uni = pa + b.area - inter;
    float lex = fminf(p.x, b.x1), ley = fminf(p.y, b.y1);
    float rex = fmaxf(p.z, b.x2), rey = fmaxf(p.w, b.y2);
    float ae = (rex - lex) * (rey - ley);
    return 1.f - __fdividef(inter * ae + uni * uni, uni * ae);
}

__device__ __forceinline__ float pow6(float x) {
    float x2 = x * x;
    return x2 * x2 * x2;
}

__device__ __forceinline__ u32 fmap(float f) {
    u32 u = __float_as_uint(f);
    return (u & 0x80000000u) ? ~u : (u | 0x80000000u);
}
__device__ __forceinline__ float fmap_inv(u32 m) {
    u32 u = (m & 0x80000000u) ? (m & 0x7fffffffu) : ~m;
    return __uint_as_float(u);
}
__device__ __forceinline__ u64 pack_key(float v, u32 idx) {
    return ((u64)fmap(v) << 32) | (u64)(0xffffffffu - idx);
}
// for values known >= 0 (alignments): single-OR monotone map
__device__ __forceinline__ u64 pack_key_pos(float v, u32 idx) {
    return ((u64)(__float_as_uint(v) | 0x80000000u) << 32) | (u64)(0xffffffffu - idx);
}

__device__ __forceinline__ u64 warp_max64(u64 v) {
#pragma unroll
    for (int off = 16; off; off >>= 1) {
        u64 o = __shfl_xor_sync(0xffffffffu, v, off);
        if (o > v) v = o;
    }
    return v;
}

// ---------------------------------------------------------------------------
// Kernel 1: fused prep. y<3: EXACT sigmoid + transpose; y==3: boxprep.
// grid (125, 4, 16), block (32, 8)
// ---------------------------------------------------------------------------
__global__ void prep_kernel(const float* __restrict__ logits,
                            const float4* __restrict__ pred_boxes) {
    int b = blockIdx.z;
    if (blockIdx.y == 3) {
        int tid = threadIdx.y * 32 + threadIdx.x;
        if (tid < 32) {
            int n = blockIdx.x * 32 + tid;
            int i = b * NP + n;
            float4 v = pred_boxes[i];
            float x1 = v.x - 0.5f * v.z, y1 = v.y - 0.5f * v.w;
            float x2 = v.x + 0.5f * v.z, y2 = v.y + 0.5f * v.w;
            g_pxyxy[i] = make_float4(x1, y1, x2, y2);
            g_parea[i] = (x2 - x1) * (y2 - y1);
        }
        return;
    }
    __shared__ float tile[32][33];
    int n0 = blockIdx.x * 32, c0 = blockIdx.y * 32;
    int tx = threadIdx.x, ty = threadIdx.y;
#pragma unroll
    for (int i = 0; i < 4; i++) {
        int c = c0 + tx;
        int n = n0 + ty + i * 8;
        float v = 0.f;
        if (c < CC) v = logits[((size_t)b * NP + n) * CC + c];
        tile[ty + i * 8][tx] = 1.f / (1.f + expf(-v));   // EXACT: shared by screen+verify
    }
    __syncthreads();
#pragma unroll
    for (int i = 0; i < 4; i++) {
        int n = n0 + tx;
        int c = c0 + ty + i * 8;
        if (c < CC) g_scores_t[((size_t)b * CC + c) * NP + n] = tile[tx][ty + i * 8];
    }
}

// ---------------------------------------------------------------------------
// Kernel 2: warp-per-(b,g). Pass 1: branchless DUAL top-3 chains over the
// lane's EVEN-j / ODD-j element subsets. Pops merge the two heads; PER-CHAIN
// refill-on-empty rescans only that parity subset, restoring the invariant
// "non-empty chain head == true next-best of its subset". Pass 2: exact
// verify (reference GIoU * srow) + 13 exact pops + scatter.
// ---------------------------------------------------------------------------
__global__ void __launch_bounds__(WPB * 32) assign_kernel(
    const float4* __restrict__ gt_boxes,
    const int* __restrict__ gt_labels)
{
    __shared__ int s_cons[WPB][KPOP];   // popped candidate pred indices

    int wid  = threadIdx.x >> 5;
    int lane = threadIdx.x & 31;
    int p = blockIdx.x * WPB + wid;     // (b,g) pair id, 0..4799
    int b = p / GG;
    int g = p - b * GG;

    Box gbb = toxyxy(gt_boxes[b * GG + g]);
    int label = gt_labels[b * GG + g];
    const float*  srow = g_scores_t + ((size_t)b * CC + label) * NP;
    const float4* pxy  = g_pxyxy + (size_t)b * NP;
    const float*  par  = g_parea + (size_t)b * NP;

    // ---- pass 1: two interleaved branchless top-3 chains (even/odd j) ----
    u32 a1 = 0u, a2 = 0u, a3 = 0u, ai1 = 0u, ai2 = 0u, ai3 = 0u;
    u32 b1 = 0u, b2 = 0u, b3 = 0u, bi1 = 0u, bi2 = 0u, bi3 = 0u;

#pragma unroll 4
    for (int j = 0; j < JPT - 1; j += 2) {
        // even j -> chain A
        {
            int n = lane + j * 32;
            float ov = approx_neg_giou(__ldg(&pxy[n]), __ldg(&par[n]), gbb);
            float al = __ldg(srow + n) * pow6(ov);
            u32 ma = __float_as_uint(al) | 0x80000000u;
            u32 mi = (u32)n;
            bool c = ma > a1;
            u32 lv = c ? a1 : ma;  u32 li = c ? ai1 : mi;
            a1 = c ? ma : a1;      ai1 = c ? mi : ai1;
            c = lv > a2;
            u32 lv2 = c ? a2 : lv; u32 li2 = c ? ai2 : li;
            a2 = c ? lv : a2;      ai2 = c ? li : ai2;
            c = lv2 > a3;
            a3 = c ? lv2 : a3;     ai3 = c ? li2 : ai3;
        }
        // odd j -> chain B
        {
            int n = lane + (j + 1) * 32;
            float ov = approx_neg_giou(__ldg(&pxy[n]), __ldg(&par[n]), gbb);
            float al = __ldg(srow + n) * pow6(ov);
            u32 ma = __float_as_uint(al) | 0x80000000u;
            u32 mi = (u32)n;
            bool c = ma > b1;
            u32 lv = c ? b1 : ma;  u32 li = c ? bi1 : mi;
            b1 = c ? ma : b1;      bi1 = c ? mi : bi1;
            c = lv > b2;
            u32 lv2 = c ? b2 : lv; u32 li2 = c ? bi2 : li;
            b2 = c ? lv : b2;      bi2 = c ? li : bi2;
            c = lv2 > b3;
            b3 = c ? lv2 : b3;     bi3 = c ? li2 : bi3;
        }
    }
    {   // tail j = JPT-1 (even) -> chain A
        int n = lane + (JPT - 1) * 32;
        float ov = approx_neg_giou(__ldg(&pxy[n]), __ldg(&par[n]), gbb);
        float al = __ldg(srow + n) * pow6(ov);
        u32 ma = __float_as_uint(al) | 0x80000000u;
        u32 mi = (u32)n;
        bool c = ma > a1;
        u32 lv = c ? a1 : ma;  u32 li = c ? ai1 : mi;
        a1 = c ? ma : a1;      ai1 = c ? mi : ai1;
        c = lv > a2;
        u32 lv2 = c ? a2 : lv; u32 li2 = c ? ai2 : li;
        a2 = c ? lv : a2;      ai2 = c ? li : ai2;
        c = lv2 > a3;
        a3 = c ? lv2 : a3;     ai3 = c ? li2 : ai3;
    }

    // ---- collect approx top-16: pops + PER-CHAIN cooperative refill ----
    int cnt = 0;
    for (int k = 0; k < KPOP; k++) {
        u32 h = (a1 > b1) ? a1 : b1;
        u32 w = __reduce_max_sync(0xffffffffu, h);
        if (w == 0u) break;                          // all caches empty
        unsigned bal = __ballot_sync(0xffffffffu, h == w);
        int owner = __ffs((int)bal) - 1;
        bool emptiedA = false, emptiedB = false;
        if (lane == owner) {
            if (a1 == w) {
                s_cons[wid][k] = (int)ai1;
                a1 = a2; ai1 = ai2; a2 = a3; ai2 = ai3; a3 = 0u;
                emptiedA = (a1 == 0u);
            } else {
                s_cons[wid][k] = (int)bi1;
                b1 = b2; bi1 = bi2; b2 = b3; bi2 = bi3; b3 = 0u;
                emptiedB = (b1 == 0u);
            }
        }
        cnt++;
        __syncwarp();

        if (k < KPOP - 1) {
            unsigned needA = __ballot_sync(0xffffffffu, emptiedA);
            unsigned needB = __ballot_sync(0xffffffffu, emptiedB);
            // refill chain A (even-j subset) of the owner lane
            if (needA) {
                int ol = __ffs((int)needA) - 1;
                u32 bm = 0u, bi = 0u;
#pragma unroll
                for (int m = 0; m < 2; m++) {
                    int j = 2 * (lane + m * 32);      // even j
                    if (j < JPT) {
                        int n = ol + j * 32;
                        bool cons = false;
                        for (int t = 0; t <= k; t++)
                            if (s_cons[wid][t] == n) cons = true;
                        if (!cons) {
                            float ov = approx_neg_giou(__ldg(&pxy[n]), __ldg(&par[n]), gbb);
                            float al = __ldg(srow + n) * pow6(ov);
                            u32 ma = __float_as_uint(al) | 0x80000000u;
                            if (ma > bm) { bm = ma; bi = (u32)n; }
                        }
                    }
                }
#pragma unroll
                for (int off = 16; off; off >>= 1) {
                    u32 om = __shfl_xor_sync(0xffffffffu, bm, off);
                    u32 oi = __shfl_xor_sync(0xffffffffu, bi, off);
                    if (om > bm) { bm = om; bi = oi; }
                }
                if (lane == ol) { a1 = bm; ai1 = bi; }
            }
            // refill chain B (odd-j subset) of the owner lane
            if (needB) {
                int ol = __ffs((int)needB) - 1;
                u32 bm = 0u, bi = 0u;
#pragma unroll
                for (int m = 0; m < 2; m++) {
                    int j = 2 * (lane + m * 32) + 1;  // odd j
                    if (j < JPT) {
                        int n = ol + j * 32;
                        bool cons = false;
                        for (int t = 0; t <= k; t++)
                            if (s_cons[wid][t] == n) cons = true;
                        if (!cons) {
                            float ov = approx_neg_giou(__ldg(&pxy[n]), __ldg(&par[n]), gbb);
                            float al = __ldg(srow + n) * pow6(ov);
                            u32 ma = __float_as_uint(al) | 0x80000000u;
                            if (ma > bm) { bm = ma; bi = (u32)n; }
                        }
                    }
                }
#pragma unroll
                for (int off = 16; off; off >>= 1) {
                    u32 om = __shfl_xor_sync(0xffffffffu, bm, off);
                    u32 oi = __shfl_xor_sync(0xffffffffu, bi, off);
                    if (om > bm) { bm = om; bi = oi; }
                }
                if (lane == ol) { b1 = bm; bi1 = bi; }
            }
        }
    }
    __syncwarp();

    // ---- pass 2: exact evaluation of candidates, 13 exact pops, scatter ----
    int myn = (lane < cnt) ? s_cons[wid][lane] : -1;
    u64 ekey = 0ull;
    float eov = 0.f;
    if (myn >= 0) {
        eov = exact_neg_giou(__ldg(&pxy[myn]), __ldg(&par[myn]), gbb);
        float eal = __ldg(srow + myn) * pow6(eov);
        ekey = pack_key_pos(eal, (u32)myn);
    }

    u64* keyb = g_key + (size_t)b * NP;
    for (int k = 0; k < KTOP; k++) {
        u64 w = warp_max64(ekey);
        if ((u32)(w >> 32) <= 0x80000000u) break;   // best alignment <= 0
        if (ekey == w) {
            ekey = 0ull;
            atomicMax(keyb + myn, pack_key(eov, (u32)g));
        }
    }
}

// ---------------------------------------------------------------------------
// Kernel 3: finalize — decode winner from key (ov embedded), reset key.
// ---------------------------------------------------------------------------
__global__ void finalize_kernel(
    const int* __restrict__ gt_labels,
    float* __restrict__ out)
{
    int i = blockIdx.x * blockDim.x + threadIdx.x;
    if (i >= BS * NP) return;
    int b = i / NP;
    int n = i - b * NP;

    u64 key = g_key[i];
    g_key[i] = 0ull;    // reset for next graph replay
    float inds = 0.f, lab = -1.f, met = 0.f;
    if (key != 0ull) {
        int g = (int)(0xffffffffu - (u32)(key & 0xffffffffu));
        float ov = fmap_inv((u32)(key >> 32));
        int label = __ldg(gt_labels + b * GG + g);
        float s = g_scores_t[((size_t)b * CC + label) * NP + n];
        met = s * pow6(ov);
        inds = (float)(g + 1);
        lab = (float)label;
    }
    out[i] = inds;
    out[BS * NP + i] = lab;
    out[2 * BS * NP + i] = met;
}

// ---------------------------------------------------------------------------
extern "C" void kernel_launch(void* const* d_in, const int* in_sizes, int n_in,
                              void* d_out, int out_size) {
    const float*  logits     = (const float*)d_in[0];
    const float4* pred_boxes = (const float4*)d_in[1];
    const float4* gt_boxes   = (const float4*)d_in[2];
    const int*    gt_labels  = (const int*)d_in[3];
    float* out = (float*)d_out;

    dim3 pgrid(NP / 32, 4, BS);
    prep_kernel<<<pgrid, dim3(32, 8)>>>(logits, pred_boxes);
    assign_kernel<<<(BS * GG) / WPB, WPB * 32>>>(gt_boxes, gt_labels);
    finalize_kernel<<<(BS * NP + 127) / 128, 128>>>(gt_labels, out);
}